// round 1
// baseline (speedup 1.0000x reference)
#include <cuda_runtime.h>
#include <math.h>

#define NB 128
#define NT 128
#define NV 10000
#define NE 256
#define NH 1024
#define ND 128
#define NG 3072   // 3*NH

// ---------------- scratch (device globals; no cudaMalloc allowed) ----------------
__device__ float g_table[(size_t)NV * NG];        // emb@gru_k + bi   (~123 MB)
__device__ float g_hs[(size_t)NB * NT * NH];      // all hidden states [B][T][H] (~67 MB)
__device__ float g_rg[(size_t)NB * NG];           // per-step recurrent gates (1.5 MB)
__device__ float g_d[(size_t)NB * NT * ND];       // relu(hs@w1+b1) (8.4 MB)
__device__ float g_logits[(size_t)NB * NT * NV];  // logits (~655 MB)

// ---------------- generic fp32 tiled GEMM: C[M,N] = A[M,K](lda) @ B[K,N](ldb) ----
// Row clamp on A (M boundary), column clamp on B loads (N boundary), guarded stores.
// K must be a multiple of BK (true for all call sites: 256, 1024, 128).
template<int BM, int BN, int BK, int TM, int TN>
__global__ __launch_bounds__((BM/TM)*(BN/TN))
void gemm_f32(const float* __restrict__ A, int lda,
              const float* __restrict__ Bmat, int ldb,
              float* __restrict__ C, int ldc,
              int M, int N, int K,
              const float* __restrict__ bias, int relu)
{
    constexpr int THREADS = (BM/TM)*(BN/TN);
    __shared__ float As[BK][BM];
    __shared__ float Bs[BK][BN];

    const int tid = threadIdx.x;
    const int bm0 = blockIdx.y * BM;
    const int bn0 = blockIdx.x * BN;
    const int tn  = (tid % (BN/TN)) * TN;
    const int tm  = (tid / (BN/TN)) * TM;

    float acc[TM][TN];
#pragma unroll
    for (int i = 0; i < TM; i++)
#pragma unroll
        for (int j = 0; j < TN; j++) acc[i][j] = 0.0f;

    for (int k0 = 0; k0 < K; k0 += BK) {
        // A tile: BM x BK, vectorized float4 along K, transposed into As[k][m]
#pragma unroll
        for (int i = tid; i < BM*BK/4; i += THREADS) {
            int m  = i / (BK/4);
            int kk = (i % (BK/4)) * 4;
            int gm = bm0 + m; if (gm > M-1) gm = M-1;
            float4 v = *(const float4*)&A[(size_t)gm * lda + k0 + kk];
            As[kk+0][m] = v.x; As[kk+1][m] = v.y;
            As[kk+2][m] = v.z; As[kk+3][m] = v.w;
        }
        // B tile: BK x BN, vectorized float4 along N
#pragma unroll
        for (int i = tid; i < BK*BN/4; i += THREADS) {
            int kk = i / (BN/4);
            int n  = (i % (BN/4)) * 4;
            int gn = bn0 + n; if (gn > N-4) gn = N-4;   // N % 4 == 0 at all call sites
            float4 v = *(const float4*)&Bmat[(size_t)(k0+kk) * ldb + gn];
            *(float4*)&Bs[kk][n] = v;
        }
        __syncthreads();
#pragma unroll
        for (int kk = 0; kk < BK; kk++) {
            float a[TM], b[TN];
#pragma unroll
            for (int i = 0; i < TM; i++) a[i] = As[kk][tm+i];
#pragma unroll
            for (int j = 0; j < TN; j++) b[j] = Bs[kk][tn+j];
#pragma unroll
            for (int i = 0; i < TM; i++)
#pragma unroll
                for (int j = 0; j < TN; j++) acc[i][j] = fmaf(a[i], b[j], acc[i][j]);
        }
        __syncthreads();
    }

#pragma unroll
    for (int i = 0; i < TM; i++) {
        int gm = bm0 + tm + i;
        if (gm >= M) continue;
#pragma unroll
        for (int j = 0; j < TN; j++) {
            int gn = bn0 + tn + j;
            if (gn >= N) continue;
            float v = acc[i][j];
            if (bias) v += bias[gn];
            if (relu) v = fmaxf(v, 0.0f);
            C[(size_t)gm * ldc + gn] = v;
        }
    }
}

// ---------------- GRU gate fusion: reads g_rg + table gather, writes g_hs[:,t,:] --
__global__ __launch_bounds__(256)
void gru_gate(const int* __restrict__ tokens, const float* __restrict__ br, int t)
{
    int idx = blockIdx.x * 256 + threadIdx.x;     // [0, NB*NH)
    int b = idx >> 10;                            // / NH
    int j = idx & (NH - 1);                       // % NH
    int tok = tokens[b * NT + t];
    const float* tab = g_table + (size_t)tok * NG;
    float xz = tab[j], xr = tab[NH + j], xh = tab[2*NH + j];
    const float* rgp = g_rg + (size_t)b * NG;
    float rz = rgp[j]        + br[j];
    float rr = rgp[NH + j]   + br[NH + j];
    float rh = rgp[2*NH + j] + br[2*NH + j];
    float z  = 1.0f / (1.0f + expf(-(xz + rz)));
    float r  = 1.0f / (1.0f + expf(-(xr + rr)));
    float hh = tanhf(xh + r * rh);
    float hp = (t > 0) ? g_hs[((size_t)b * NT + (t-1)) * NH + j] : 0.0f;
    g_hs[((size_t)b * NT + t) * NH + j] = z * hp + (1.0f - z) * hh;
}

__global__ __launch_bounds__(256)
void zero_rg()
{
    int idx = blockIdx.x * 256 + threadIdx.x;
    if (idx < NB * NG) g_rg[idx] = 0.0f;
}

// ---------------- softmax over V per (b,t) row; row cached in smem ----------------
__global__ __launch_bounds__(256)
void softmax_rows(float* __restrict__ out)
{
    __shared__ float row[NV];
    __shared__ float red[256];
    const int tid = threadIdx.x;
    const size_t r0 = (size_t)blockIdx.x * NV;

    float m = -1e30f;
    for (int v = tid; v < NV; v += 256) {
        float x = g_logits[r0 + v];
        row[v] = x;
        m = fmaxf(m, x);
    }
    red[tid] = m; __syncthreads();
    for (int s = 128; s > 0; s >>= 1) {
        if (tid < s) red[tid] = fmaxf(red[tid], red[tid + s]);
        __syncthreads();
    }
    const float smax = red[0];
    __syncthreads();

    float sum = 0.0f;
    for (int v = tid; v < NV; v += 256) {
        float e = expf((row[v] - smax) * 50.0f);   // 1/TEMP = 50
        row[v] = e;
        sum += e;
    }
    red[tid] = sum; __syncthreads();
    for (int s = 128; s > 0; s >>= 1) {
        if (tid < s) red[tid] += red[tid + s];
        __syncthreads();
    }
    const float inv = 1.0f / red[0];
    for (int v = tid; v < NV; v += 256)
        out[r0 + v] = row[v] * inv;
}

// ---------------- launch ----------------
extern "C" void kernel_launch(void* const* d_in, const int* in_sizes, int n_in,
                              void* d_out, int out_size)
{
    const int*   tokens = (const int*)  d_in[0];
    const float* emb    = (const float*)d_in[1];
    const float* gru_k  = (const float*)d_in[2];
    const float* gru_rk = (const float*)d_in[3];
    const float* gru_bi = (const float*)d_in[4];
    const float* gru_br = (const float*)d_in[5];
    const float* w1     = (const float*)d_in[6];
    const float* b1     = (const float*)d_in[7];
    const float* w2     = (const float*)d_in[8];
    const float* b2     = (const float*)d_in[9];
    float* out = (float*)d_out;

    float* tablep = nullptr; cudaGetSymbolAddress((void**)&tablep, g_table);
    float* hsp    = nullptr; cudaGetSymbolAddress((void**)&hsp,    g_hs);
    float* rgp    = nullptr; cudaGetSymbolAddress((void**)&rgp,    g_rg);
    float* dp     = nullptr; cudaGetSymbolAddress((void**)&dp,     g_d);
    float* logp   = nullptr; cudaGetSymbolAddress((void**)&logp,   g_logits);

    // 1) table = emb @ gru_k + gru_bi        [NV, NG], K=NE
    {
        dim3 grid(NG/64, (NV + 127)/128);
        gemm_f32<128,64,16,8,4><<<grid, 256>>>(emb, NE, gru_k, NG, tablep, NG,
                                               NV, NG, NE, gru_bi, 0);
    }

    // 2) GRU scan: t=0 uses rg=0; t>0 does rg = h_{t-1} @ gru_rk
    zero_rg<<<(NB*NG + 255)/256, 256>>>();
    gru_gate<<<(NB*NH)/256, 256>>>(tokens, gru_br, 0);
    for (int t = 1; t < NT; t++) {
        dim3 grid(NG/64, NB/64);   // 48 x 2
        gemm_f32<64,64,16,4,4><<<grid, 256>>>(hsp + (size_t)(t-1)*NH, NT*NH,
                                              gru_rk, NG, rgp, NG,
                                              NB, NG, NH, nullptr, 0);
        gru_gate<<<(NB*NH)/256, 256>>>(tokens, gru_br, t);
    }

    // 3) d = relu(hs @ w1 + b1)              [NB*NT, ND], K=NH
    {
        dim3 grid(ND/64, (NB*NT)/128);   // 2 x 128
        gemm_f32<128,64,16,8,4><<<grid, 256>>>(hsp, NH, w1, ND, dp, ND,
                                               NB*NT, ND, NH, b1, 1);
    }

    // 4) logits = d @ w2 + b2                [NB*NT, NV], K=ND
    {
        dim3 grid((NV + 63)/64, (NB*NT)/128);   // 157 x 128
        gemm_f32<128,64,16,8,4><<<grid, 256>>>(dp, ND, w2, NV, logp, NV,
                                               NB*NT, NV, ND, b2, 0);
    }

    // 5) softmax over V, one block per (b,t) row
    softmax_rows<<<NB*NT, 256>>>(out);
}

// round 2
// speedup vs baseline: 1.5856x; 1.5856x over previous
#include <cuda_runtime.h>
#include <math.h>

#define NB 128
#define NT 128
#define NV 10000
#define NE 256
#define NH 1024
#define ND 128
#define NG 3072   // 3*NH

#define NBLK 128        // persistent blocks (== NB*? no: column partition), all co-resident
#define KC   64         // K chunk for h staging
#define W_LD 1028       // padded weight row stride (floats): bank-conflict-free LDS.64
#define H_LD 68         // padded h chunk row stride (floats)

typedef unsigned long long u64;

// ---------------- scratch (device globals; no cudaMalloc allowed) ----------------
__device__ float g_table[(size_t)NV * NG];        // emb@gru_k + bi   (~123 MB)
__device__ float g_hs[(size_t)NB * NT * NH];      // hidden states [B][T][H] (~67 MB)
__device__ float g_d[(size_t)NB * NT * ND];       // relu(hs@w1+b1) (8.4 MB)
__device__ float g_logits[(size_t)NB * NT * NV];  // logits (~655 MB)
__device__ unsigned g_barcnt;

// ---------------- generic fp32 tiled GEMM (unchanged from R1) --------------------
template<int BM, int BN, int BK, int TM, int TN>
__global__ __launch_bounds__((BM/TM)*(BN/TN))
void gemm_f32(const float* __restrict__ A, int lda,
              const float* __restrict__ Bmat, int ldb,
              float* __restrict__ C, int ldc,
              int M, int N, int K,
              const float* __restrict__ bias, int relu)
{
    constexpr int THREADS = (BM/TM)*(BN/TN);
    __shared__ float As[BK][BM];
    __shared__ float Bs[BK][BN];

    const int tid = threadIdx.x;
    const int bm0 = blockIdx.y * BM;
    const int bn0 = blockIdx.x * BN;
    const int tn  = (tid % (BN/TN)) * TN;
    const int tm  = (tid / (BN/TN)) * TM;

    float acc[TM][TN];
#pragma unroll
    for (int i = 0; i < TM; i++)
#pragma unroll
        for (int j = 0; j < TN; j++) acc[i][j] = 0.0f;

    for (int k0 = 0; k0 < K; k0 += BK) {
#pragma unroll
        for (int i = tid; i < BM*BK/4; i += THREADS) {
            int m  = i / (BK/4);
            int kk = (i % (BK/4)) * 4;
            int gm = bm0 + m; if (gm > M-1) gm = M-1;
            float4 v = *(const float4*)&A[(size_t)gm * lda + k0 + kk];
            As[kk+0][m] = v.x; As[kk+1][m] = v.y;
            As[kk+2][m] = v.z; As[kk+3][m] = v.w;
        }
#pragma unroll
        for (int i = tid; i < BK*BN/4; i += THREADS) {
            int kk = i / (BN/4);
            int n  = (i % (BN/4)) * 4;
            int gn = bn0 + n; if (gn > N-4) gn = N-4;
            float4 v = *(const float4*)&Bmat[(size_t)(k0+kk) * ldb + gn];
            *(float4*)&Bs[kk][n] = v;
        }
        __syncthreads();
#pragma unroll
        for (int kk = 0; kk < BK; kk++) {
            float a[TM], b[TN];
#pragma unroll
            for (int i = 0; i < TM; i++) a[i] = As[kk][tm+i];
#pragma unroll
            for (int j = 0; j < TN; j++) b[j] = Bs[kk][tn+j];
#pragma unroll
            for (int i = 0; i < TM; i++)
#pragma unroll
                for (int j = 0; j < TN; j++) acc[i][j] = fmaf(a[i], b[j], acc[i][j]);
        }
        __syncthreads();
    }

#pragma unroll
    for (int i = 0; i < TM; i++) {
        int gm = bm0 + tm + i;
        if (gm >= M) continue;
#pragma unroll
        for (int j = 0; j < TN; j++) {
            int gn = bn0 + tn + j;
            if (gn >= N) continue;
            float v = acc[i][j];
            if (bias) v += bias[gn];
            if (relu) v = fmaxf(v, 0.0f);
            C[(size_t)gm * ldc + gn] = v;
        }
    }
}

// ---------------- persistent GRU scan ------------------------------------------
__global__ void reset_bar() { g_barcnt = 0u; }

__device__ __forceinline__ void ffma2(u64& d, u64 a, u64 b) {
    asm("fma.rn.f32x2 %0, %1, %2, %0;" : "+l"(d) : "l"(a), "l"(b));
}

// smem: w_s[24][W_LD]  (24 gate-cols x 1024 K, padded), then 2 h buffers [128][H_LD]
#define W_FLOATS (24 * W_LD)
#define HBUF_FLOATS (128 * H_LD)
#define PERSIST_SMEM_BYTES ((W_FLOATS + 2 * HBUF_FLOATS) * 4)

__global__ __launch_bounds__(256, 1)
void gru_persist(const int* __restrict__ tokens,
                 const float* __restrict__ gru_rk,
                 const float* __restrict__ br)
{
    extern __shared__ float sm[];
    float* w_s = sm;                       // [c=24][W_LD]
    float* h_b = sm + W_FLOATS;            // 2 x [128][H_LD]

    const int tid = threadIdx.x;
    const int bid = blockIdx.x;
    const int j   = tid & 7;               // local h-col
    const int rg4 = tid >> 3;              // 0..31 (row group)
    const int jb  = bid * 8;               // global h-col base

    // ---- load resident weight slice: w_s[c][k] = rk[k][(c>>3)*NH + jb + (c&7)]
    for (int idx = tid; idx < 1024 * 24; idx += 256) {
        int k = idx & 1023;
        int c = idx >> 10;                 // 0..23
        w_s[c * W_LD + k] = gru_rk[(size_t)k * NG + (c >> 3) * NH + jb + (c & 7)];
    }
    const float brz = br[jb + j];
    const float brr = br[NH + jb + j];
    const float brh = br[2*NH + jb + j];
    __syncthreads();

    // stage-thread mapping: lane covers k (16 float4 = 64 floats), brow covers rows
    const int s_lane  = tid & 15;          // k quad 0..15
    const int s_brow0 = tid >> 4;          // 0..15

    for (int t = 0; t < NT; t++) {
        u64 acc2[4][3];
#pragma unroll
        for (int i = 0; i < 4; i++)
#pragma unroll
            for (int g = 0; g < 3; g++) acc2[i][g] = 0ull;

        if (t > 0) {
            const float* hprev_base = g_hs;  // row b at (b*NT + t-1)*NH
            float4 pre[8];

            // prologue: chunk 0 -> regs -> buf0
#pragma unroll
            for (int r = 0; r < 8; r++) {
                int bb = s_brow0 + 16 * r;
                pre[r] = __ldcg((const float4*)&hprev_base[((size_t)bb * NT + (t-1)) * NH + s_lane * 4]);
            }
#pragma unroll
            for (int r = 0; r < 8; r++) {
                int bb = s_brow0 + 16 * r;
                *(float4*)&h_b[bb * H_LD + s_lane * 4] = pre[r];
            }
            __syncthreads();

            for (int c = 0; c < NH / KC; c++) {
                // prefetch next chunk
                if (c + 1 < NH / KC) {
#pragma unroll
                    for (int r = 0; r < 8; r++) {
                        int bb = s_brow0 + 16 * r;
                        pre[r] = __ldcg((const float4*)&hprev_base[((size_t)bb * NT + (t-1)) * NH
                                                                   + (c+1) * KC + s_lane * 4]);
                    }
                }
                // compute on buffer c&1
                const float* hb = h_b + (c & 1) * HBUF_FLOATS;
                const int kg = c * KC;     // global k base of this chunk
#pragma unroll 4
                for (int kk = 0; kk < KC; kk += 2) {
                    u64 w0 = *(const u64*)&w_s[(0*8 + j) * W_LD + kg + kk];
                    u64 w1 = *(const u64*)&w_s[(1*8 + j) * W_LD + kg + kk];
                    u64 w2 = *(const u64*)&w_s[(2*8 + j) * W_LD + kg + kk];
#pragma unroll
                    for (int i = 0; i < 4; i++) {
                        u64 h2 = *(const u64*)&hb[(rg4 + 32*i) * H_LD + kk];
                        ffma2(acc2[i][0], h2, w0);
                        ffma2(acc2[i][1], h2, w1);
                        ffma2(acc2[i][2], h2, w2);
                    }
                }
                __syncthreads();
                if (c + 1 < NH / KC) {
                    float* nb = h_b + ((c + 1) & 1) * HBUF_FLOATS;
#pragma unroll
                    for (int r = 0; r < 8; r++) {
                        int bb = s_brow0 + 16 * r;
                        *(float4*)&nb[bb * H_LD + s_lane * 4] = pre[r];
                    }
                    __syncthreads();
                }
            }
        }

        // ---- gates + h_t write (thread owns rows rg4+32i, col jb+j)
#pragma unroll
        for (int i = 0; i < 4; i++) {
            int b = rg4 + 32 * i;
            float rz = __uint_as_float((unsigned)acc2[i][0])
                     + __uint_as_float((unsigned)(acc2[i][0] >> 32)) + brz;
            float rr = __uint_as_float((unsigned)acc2[i][1])
                     + __uint_as_float((unsigned)(acc2[i][1] >> 32)) + brr;
            float rh = __uint_as_float((unsigned)acc2[i][2])
                     + __uint_as_float((unsigned)(acc2[i][2] >> 32)) + brh;
            int tok = tokens[b * NT + t];
            const float* tab = g_table + (size_t)tok * NG + jb + j;
            float xz = tab[0], xr = tab[NH], xh = tab[2*NH];
            float z  = 1.0f / (1.0f + expf(-(xz + rz)));
            float r  = 1.0f / (1.0f + expf(-(xr + rr)));
            float hh = tanhf(xh + r * rh);
            float hp = (t > 0) ? __ldcg(&g_hs[((size_t)b * NT + (t-1)) * NH + jb + j]) : 0.0f;
            g_hs[((size_t)b * NT + t) * NH + jb + j] = z * hp + (1.0f - z) * hh;
        }

        // ---- grid barrier (monotonic counter; reset by reset_bar each launch)
        __syncthreads();
        if (tid == 0) {
            __threadfence();
            atomicAdd(&g_barcnt, 1u);
            const unsigned target = (unsigned)NBLK * (unsigned)(t + 1);
            while (atomicAdd(&g_barcnt, 0u) < target) { }
        }
        __syncthreads();
    }
}

// ---------------- softmax over V per (b,t) row (unchanged) ----------------------
__global__ __launch_bounds__(256)
void softmax_rows(float* __restrict__ out)
{
    __shared__ float row[NV];
    __shared__ float red[256];
    const int tid = threadIdx.x;
    const size_t r0 = (size_t)blockIdx.x * NV;

    float m = -1e30f;
    for (int v = tid; v < NV; v += 256) {
        float x = g_logits[r0 + v];
        row[v] = x;
        m = fmaxf(m, x);
    }
    red[tid] = m; __syncthreads();
    for (int s = 128; s > 0; s >>= 1) {
        if (tid < s) red[tid] = fmaxf(red[tid], red[tid + s]);
        __syncthreads();
    }
    const float smax = red[0];
    __syncthreads();

    float sum = 0.0f;
    for (int v = tid; v < NV; v += 256) {
        float e = expf((row[v] - smax) * 50.0f);   // 1/TEMP
        row[v] = e;
        sum += e;
    }
    red[tid] = sum; __syncthreads();
    for (int s = 128; s > 0; s >>= 1) {
        if (tid < s) red[tid] += red[tid + s];
        __syncthreads();
    }
    const float inv = 1.0f / red[0];
    for (int v = tid; v < NV; v += 256)
        out[r0 + v] = row[v] * inv;
}

// ---------------- launch ----------------
extern "C" void kernel_launch(void* const* d_in, const int* in_sizes, int n_in,
                              void* d_out, int out_size)
{
    const int*   tokens = (const int*)  d_in[0];
    const float* emb    = (const float*)d_in[1];
    const float* gru_k  = (const float*)d_in[2];
    const float* gru_rk = (const float*)d_in[3];
    const float* gru_bi = (const float*)d_in[4];
    const float* gru_br = (const float*)d_in[5];
    const float* w1     = (const float*)d_in[6];
    const float* b1     = (const float*)d_in[7];
    const float* w2     = (const float*)d_in[8];
    const float* b2     = (const float*)d_in[9];
    float* out = (float*)d_out;

    float* tablep = nullptr; cudaGetSymbolAddress((void**)&tablep, g_table);
    float* hsp    = nullptr; cudaGetSymbolAddress((void**)&hsp,    g_hs);
    float* dp     = nullptr; cudaGetSymbolAddress((void**)&dp,     g_d);
    float* logp   = nullptr; cudaGetSymbolAddress((void**)&logp,   g_logits);

    static int smem_set = 0;
    if (!smem_set) {
        cudaFuncSetAttribute(gru_persist, cudaFuncAttributeMaxDynamicSharedMemorySize,
                             PERSIST_SMEM_BYTES);
        smem_set = 1;
    }

    // 1) table = emb @ gru_k + gru_bi        [NV, NG], K=NE
    {
        dim3 grid(NG/64, (NV + 127)/128);
        gemm_f32<128,64,16,8,4><<<grid, 256>>>(emb, NE, gru_k, NG, tablep, NG,
                                               NV, NG, NE, gru_bi, 0);
    }

    // 2) persistent GRU scan (fused recurrent GEMM + gates, grid barrier per step)
    reset_bar<<<1, 1>>>();
    gru_persist<<<NBLK, 256, PERSIST_SMEM_BYTES>>>(tokens, gru_rk, gru_br);

    // 3) d = relu(hs @ w1 + b1)              [NB*NT, ND], K=NH
    {
        dim3 grid(ND/64, (NB*NT)/128);
        gemm_f32<128,64,16,8,4><<<grid, 256>>>(hsp, NH, w1, ND, dp, ND,
                                               NB*NT, ND, NH, b1, 1);
    }

    // 4) logits = d @ w2 + b2                [NB*NT, NV], K=ND
    {
        dim3 grid((NV + 63)/64, (NB*NT)/128);
        gemm_f32<128,64,16,8,4><<<grid, 256>>>(dp, ND, w2, NV, logp, NV,
                                               NB*NT, NV, ND, b2, 0);
    }

    // 5) softmax over V
    softmax_rows<<<NB*NT, 256>>>(out);
}